// round 7
// baseline (speedup 1.0000x reference)
#include <cuda_runtime.h>

// Allpass biquad, fs=16000, f0=4000, Q=0.707. w0 = pi/2 exactly ->
// normalized: b0 = a2 = c, b2 = 1, b1 = a1 ~ 6e-17 (dropped).
// Closed FIR form: y[n] = c*x[n] + (1-c^2)*S[n],
//   S[n] = sum_{m=0..5} (-c)^m x[n-2-2m]    (tail (1-c^2)c^6 ~ 2.4e-5 << 1e-3)
//
// One output float4 per thread; window = 4 contiguous float4s. Interior
// threads (ov >= 3, all but one warp per sequence) take an unpredicated
// fast path: one base address + 4 LDG.128 with immediate offsets.

#define C_C  0.17149858514250882f
#define C_OM 0.97058823630252067f   /* 1 - c^2 */

#define THREADS 256

__global__ __launch_bounds__(THREADS)
void allpass_fir4(const float4* __restrict__ x4,
                  float4* __restrict__ y4,
                  int TV)                            // float4s per sequence
{
    const int ov = blockIdx.x * THREADS + threadIdx.x;   // output float4 index
    if (ov >= TV) return;
    const int idx = blockIdx.y * TV + ov;                // fits in int32 (7.68M)

    const float4* p = x4 + idx;

    float4 v0, v1, v2, v3;
    if (ov >= 3) {
        // fast path: 4 LDG.128, immediate offsets off one address
        v0 = __ldg(p - 3);
        v1 = __ldg(p - 2);
        v2 = __ldg(p - 1);
        v3 = __ldg(p);
    } else {
        // sequence head: zero-pad = zero initial filter state
        const float4 z = make_float4(0.f, 0.f, 0.f, 0.f);
        v0 = (ov >= 3) ? __ldg(p - 3) : z;
        v1 = (ov >= 2) ? __ldg(p - 2) : z;
        v2 = (ov >= 1) ? __ldg(p - 1) : z;
        v3 = __ldg(p);
    }

    // w[0..15] = x[4*ov-12 .. 4*ov+3]
    const float w0  = v0.x, w1  = v0.y, w2  = v0.z, w3  = v0.w;
    const float w4  = v1.x, w5  = v1.y, w6  = v1.z, w7  = v1.w;
    const float w8  = v2.x, w9  = v2.y, w10 = v2.z, w11 = v2.w;
    const float w12 = v3.x, w13 = v3.y, w14 = v3.z, w15 = v3.w;

    // S_i = sum_{m=0..5} (-c)^m w[10+i-2m]; Horner (even/odd), then recurrence
    float S0 = w0;
    float S1 = w1;
    S0 = fmaf(-C_C, S0, w2);   S1 = fmaf(-C_C, S1, w3);
    S0 = fmaf(-C_C, S0, w4);   S1 = fmaf(-C_C, S1, w5);
    S0 = fmaf(-C_C, S0, w6);   S1 = fmaf(-C_C, S1, w7);
    S0 = fmaf(-C_C, S0, w8);   S1 = fmaf(-C_C, S1, w9);
    S0 = fmaf(-C_C, S0, w10);  S1 = fmaf(-C_C, S1, w11);
    const float S2 = fmaf(-C_C, S0, w12);   // S_i = x[n-2] - c*S_{i-2}
    const float S3 = fmaf(-C_C, S1, w13);

    float4 o;
    o.x = fmaf(C_OM, S0, C_C * w12);
    o.y = fmaf(C_OM, S1, C_C * w13);
    o.z = fmaf(C_OM, S2, C_C * w14);
    o.w = fmaf(C_OM, S3, C_C * w15);

    __stcs(y4 + idx, o);     // streaming store: keep L2 for x-window reuse
}

extern "C" void kernel_launch(void* const* d_in, const int* in_sizes, int n_in,
                              void* d_out, int out_size)
{
    const float4* x = (const float4*)d_in[0];
    float4*       y = (float4*)d_out;

    const int B  = 64;                   // fixed shape [64, 1, 480000]
    const int T  = in_sizes[0] / B;
    const int TV = T >> 2;               // 120000 float4s per sequence

    dim3 grid((TV + THREADS - 1) / THREADS, B, 1);
    allpass_fir4<<<grid, THREADS>>>(x, y, TV);
}

// round 8
// speedup vs baseline: 1.0357x; 1.0357x over previous
#include <cuda_runtime.h>

// Allpass biquad, fs=16000, f0=4000, Q=0.707. w0 = pi/2 exactly ->
// normalized: b0 = a2 = c, b2 = 1, b1 = a1 ~ 6e-17 (dropped).
// Closed FIR form: y[n] = c*x[n] + (1-c^2)*S[n],
//   S[n] = sum_{m=0..5} (-c)^m x[n-2-2m]    (tail (1-c^2)c^6 ~ 2.4e-5 << 1e-3)
//
// 8 outputs per thread: window = x[n0-12 .. n0+7] = 5 contiguous float4s,
// 5 LDG.128 + 2 STG.128 per 8 samples -> 0.109 L1 wavefronts/sample
// (vs 0.156 at 4 outputs/thread). Interior threads fully unpredicated.

#define C_C  0.17149858514250882f
#define C_OM 0.97058823630252067f   /* 1 - c^2 */

#define THREADS 256

__global__ __launch_bounds__(THREADS)
void allpass_fir8(const float4* __restrict__ x4,
                  float4* __restrict__ y4,
                  int NV8)                          // float8-chunks per sequence
{
    const int o8 = blockIdx.x * THREADS + threadIdx.x;   // chunk index
    if (o8 >= NV8) return;

    const int f0  = 2 * o8;                              // first output float4
    const int idx = blockIdx.y * (NV8 * 2) + f0;         // fits int32 (7.68M)

    const float4* p = x4 + idx;

    float4 v0, v1, v2, v3, v4;
    if (f0 >= 3) {
        v0 = __ldg(p - 3);
        v1 = __ldg(p - 2);
        v2 = __ldg(p - 1);
        v3 = __ldg(p);
        v4 = __ldg(p + 1);
    } else {
        // sequence head (first thread only): zero-pad = zero initial state
        const float4 z = make_float4(0.f, 0.f, 0.f, 0.f);
        v0 = z;
        v1 = (f0 >= 2) ? __ldg(p - 2) : z;
        v2 = (f0 >= 1) ? __ldg(p - 1) : z;
        v3 = __ldg(p);
        v4 = __ldg(p + 1);
    }

    // w[0..19] = x[n0-12 .. n0+7]
    const float w0  = v0.x, w1  = v0.y, w2  = v0.z, w3  = v0.w;
    const float w4  = v1.x, w5  = v1.y, w6  = v1.z, w7  = v1.w;
    const float w8  = v2.x, w9  = v2.y, w10 = v2.z, w11 = v2.w;
    const float w12 = v3.x, w13 = v3.y, w14 = v3.z, w15 = v3.w;
    const float w16 = v4.x, w17 = v4.y, w18 = v4.z, w19 = v4.w;

    // S_i = sum_{m=0..5} (-c)^m w[10+i-2m]; Horner for i=0,1, then recurrence
    float S0 = w0;
    float S1 = w1;
    S0 = fmaf(-C_C, S0, w2);   S1 = fmaf(-C_C, S1, w3);
    S0 = fmaf(-C_C, S0, w4);   S1 = fmaf(-C_C, S1, w5);
    S0 = fmaf(-C_C, S0, w6);   S1 = fmaf(-C_C, S1, w7);
    S0 = fmaf(-C_C, S0, w8);   S1 = fmaf(-C_C, S1, w9);
    S0 = fmaf(-C_C, S0, w10);  S1 = fmaf(-C_C, S1, w11);
    const float S2 = fmaf(-C_C, S0, w12);   // S_i = w[10+i] - c*S_{i-2}
    const float S3 = fmaf(-C_C, S1, w13);
    const float S4 = fmaf(-C_C, S2, w14);
    const float S5 = fmaf(-C_C, S3, w15);
    const float S6 = fmaf(-C_C, S4, w16);
    const float S7 = fmaf(-C_C, S5, w17);

    float4 o0, o1;
    o0.x = fmaf(C_OM, S0, C_C * w12);
    o0.y = fmaf(C_OM, S1, C_C * w13);
    o0.z = fmaf(C_OM, S2, C_C * w14);
    o0.w = fmaf(C_OM, S3, C_C * w15);
    o1.x = fmaf(C_OM, S4, C_C * w16);
    o1.y = fmaf(C_OM, S5, C_C * w17);
    o1.z = fmaf(C_OM, S6, C_C * w18);
    o1.w = fmaf(C_OM, S7, C_C * w19);

    __stcs(y4 + idx,     o0);    // streaming stores: keep L2 for x reuse
    __stcs(y4 + idx + 1, o1);
}

extern "C" void kernel_launch(void* const* d_in, const int* in_sizes, int n_in,
                              void* d_out, int out_size)
{
    const float4* x = (const float4*)d_in[0];
    float4*       y = (float4*)d_out;

    const int B   = 64;                  // fixed shape [64, 1, 480000]
    const int T   = in_sizes[0] / B;
    const int NV8 = T >> 3;              // 60000 float8-chunks per sequence

    dim3 grid((NV8 + THREADS - 1) / THREADS, B, 1);
    allpass_fir8<<<grid, THREADS>>>(x, y, NV8);
}